// round 9
// baseline (speedup 1.0000x reference)
#include <cuda_runtime.h>
#include <cstdint>
#include <cstddef>

#define NB 4
#define NN 2048
#define CTAB 37                 // CTAs per batch
#define NCTA (NB * CTAB)        // 148 = one per SM
#define TPB 896                 // 28 warps = 7 col-groups x 4 range-splits
#define NSPL 4
#define CPC 56                  // columns per CTA (last CTA of batch: 32)
#define NITS_K 50

typedef unsigned long long u64;

constexpr float C_EPS  = 0.1f;
constexpr float C_TOL  = 1e-3f;
constexpr float C_L2E  = 1.4426950408889634f;
constexpr float C_KK   = C_L2E / C_EPS;
constexpr float C_2K   = 2.0f * C_KK;
constexpr float C_INVK = C_EPS / C_L2E;
constexpr float C_LN2  = 0.6931471805599453f;
constexpr float C_AL2E = -2.0f;                  // log2(1/4)

struct ScratchT {
    unsigned barcnt;
    unsigned pad[31];
    float AU1[NB * NN];
    float BU1[NB * NN];
    float AU2[NB * NN];
    float BU2[NB * NN];
    float errA[2 * NITS_K * NB];
    float errB[2 * NITS_K * NB];
    unsigned mvA[2 * NITS_K * NB];
    unsigned mvB[2 * NITS_K * NB];
    float cost[2 * NB];
    float cham[2 * NB];
};
__device__ ScratchT g_s;

__device__ __forceinline__ float ex2f_(float x) {
    float y; asm("ex2.approx.ftz.f32 %0, %1;" : "=f"(y) : "f"(x)); return y;
}
__device__ __forceinline__ float lg2f_(float x) {
    float y; asm("lg2.approx.f32 %0, %1;" : "=f"(y) : "f"(x)); return y;
}
__device__ __forceinline__ u64 pk2(float lo, float hi) {
    u64 r; asm("mov.b64 %0, {%1, %2};" : "=l"(r) : "f"(lo), "f"(hi)); return r;
}
__device__ __forceinline__ void upk(u64 v, float& lo, float& hi) {
    asm("mov.b64 {%0, %1}, %2;" : "=f"(lo), "=f"(hi) : "l"(v));
}
__device__ __forceinline__ u64 pfma(u64 a, u64 b, u64 c) {
    u64 d; asm("fma.rn.f32x2 %0, %1, %2, %3;" : "=l"(d) : "l"(a), "l"(b), "l"(c)); return d;
}
__device__ __forceinline__ u64 padd(u64 a, u64 b) {
    u64 d; asm("add.rn.f32x2 %0, %1, %2;" : "=l"(d) : "l"(a), "l"(b)); return d;
}
__device__ __forceinline__ unsigned encf(float f) {
    unsigned u = __float_as_uint(f);
    return (u & 0x80000000u) ? ~u : (u | 0x80000000u);
}
__device__ __forceinline__ float decf(unsigned e) {
    return (e & 0x80000000u) ? __uint_as_float(e & 0x7fffffffu) : __uint_as_float(~e);
}

// grid barrier: 148 CTAs, one per SM. Single monotonic counter.
__device__ __forceinline__ void grid_barrier(unsigned& lb) {
    __syncthreads();
    lb++;
    if (threadIdx.x == 0) {
        unsigned target = lb * (unsigned)NCTA;
        asm volatile("red.release.gpu.global.add.u32 [%0], %1;"
                     :: "l"(&g_s.barcnt), "r"(1u) : "memory");
        unsigned v;
        do {
            asm volatile("ld.acquire.gpu.global.u32 %0, [%1];"
                         : "=r"(v) : "l"(&g_s.barcnt) : "memory");
        } while (v < target);
    }
    __syncthreads();
}

// 8-column log-sum-exp partial sums over one quarter of the row cloud.
// Column-pair packed f32x2 math; lane0 stores 8 partials to sPartG[split*8..].
__device__ __forceinline__ void col_sums8(
    const float2* __restrict__ rXY, const float2* __restrict__ sZU,
    const float2* __restrict__ cXY, const float* __restrict__ cZ,
    float Mv, float* __restrict__ sPartG, int j0, int split, int lane)
{
    u64 qx2[4], qy2[4], qz2[4], dj2[4];
    float sal[8];
#pragma unroll
    for (int p = 0; p < 4; p++) {
        float2 qa = cXY[j0 + 2 * p], qb = cXY[j0 + 2 * p + 1];
        float za = cZ[j0 + 2 * p], zb = cZ[j0 + 2 * p + 1];
        float qqa = fmaf(qa.x, qa.x, fmaf(qa.y, qa.y, za * za));
        float qqb = fmaf(qb.x, qb.x, fmaf(qb.y, qb.y, zb * zb));
        qx2[p] = pk2(qa.x * C_2K, qb.x * C_2K);
        qy2[p] = pk2(qa.y * C_2K, qb.y * C_2K);
        qz2[p] = pk2(za * C_2K, zb * C_2K);
        dj2[p] = pk2(-C_KK * qqa - Mv, -C_KK * qqb - Mv);
        sal[2 * p] = 0.f; sal[2 * p + 1] = 0.f;
    }
    int idx = split * (NN / NSPL) + lane;
#pragma unroll 4
    for (int k = 0; k < NN / NSPL / 32; k++, idx += 32) {
        float2 xy = rXY[idx];
        float2 zu = sZU[idx];
        u64 X2 = pk2(xy.x, xy.x), Y2 = pk2(xy.y, xy.y);
        u64 Z2 = pk2(zu.x, zu.x), U2 = pk2(zu.y, zu.y);
#pragma unroll
        for (int p = 0; p < 4; p++) {
            u64 t0 = padd(U2, dj2[p]);
            t0 = pfma(Z2, qz2[p], t0);
            t0 = pfma(Y2, qy2[p], t0);
            t0 = pfma(X2, qx2[p], t0);
            float lo, hi; upk(t0, lo, hi);
            sal[2 * p]     += ex2f_(lo);
            sal[2 * p + 1] += ex2f_(hi);
        }
    }
#pragma unroll
    for (int o = 16; o > 0; o >>= 1)
#pragma unroll
        for (int c = 0; c < 8; c++)
            sal[c] += __shfl_xor_sync(0xffffffffu, sal[c], o);
    if (lane == 0) {
#pragma unroll
        for (int c = 0; c < 8; c++)
            sPartG[split * 8 + c] = sal[c];
    }
}

// Epilogue for one group's 8 columns: fold splits, finish lse, write u'-form
// potential, accumulate |delta v| and new max-p.
__device__ __forceinline__ void epi8(
    const float* __restrict__ sPartG, float Mv,
    const float2* __restrict__ cXY, const float* __restrict__ cZ,
    int j0, int lane, float* __restrict__ dstU, bool firstDst,
    float* errSlot, unsigned* mvDst)
{
    float e = 0.f, pm = -3.4e38f;
    if (lane < 8) {
        float s = sPartG[lane] + sPartG[8 + lane]
                + sPartG[16 + lane] + sPartG[24 + lane];
        s = fmaxf(s, 1e-35f);
        float L = Mv + lg2f_(s);
        float pnew = C_AL2E - L;
        float2 q = cXY[j0 + lane]; float z = cZ[j0 + lane];
        float qq = fmaf(q.x, q.x, fmaf(q.y, q.y, z * z));
        float unew = pnew - C_KK * qq;
        float pold = firstDst ? C_AL2E
                              : (__ldcg(dstU + j0 + lane) + C_KK * qq);
        e = fabsf(pnew - pold);
        pm = pnew;
        __stcg(dstU + j0 + lane, unew);
    }
#pragma unroll
    for (int o = 16; o > 0; o >>= 1) {
        e += __shfl_xor_sync(0xffffffffu, e, o);
        pm = fmaxf(pm, __shfl_xor_sync(0xffffffffu, pm, o));
    }
    if (lane == 0) {
        atomicAdd(errSlot, e * C_LN2);
        atomicMax(mvDst, encf(pm));
    }
}

// Fused half-update for both interleaved Sinkhorn runs: one phase-1 section,
// one sync, back-to-back inner loops (MUFU stays saturated), one sync, one
// fused epilogue. Caller's grid_barrier supplies the trailing sync.
__device__ void dual_half(
    bool act1,
    const float2* r1XY, const float* r1Z, const float2* c1XY, const float* c1Z,
    const float* src1, float* dst1,
    const unsigned* mvS1, unsigned* mvD1, float* err1, bool fs1, bool fd1,
    bool act2,
    const float2* r2XY, const float* r2Z, const float2* c2XY, const float* c2Z,
    const float* src2, float* dst2,
    const unsigned* mvS2, unsigned* mvD2, float* err2, bool fs2, bool fd2,
    float2* sZU1, float2* sZU2, float* sPart, int colbase)
{
    const int tid = threadIdx.x;
    float Mv1 = C_AL2E, Mv2 = C_AL2E;

    if (act1) {
        if (fs1) {
            for (int t = tid; t < NN; t += TPB) {
                float2 xy = r1XY[t]; float z = r1Z[t];
                sZU1[t] = make_float2(z,
                    C_AL2E - C_KK * fmaf(xy.x, xy.x, fmaf(xy.y, xy.y, z * z)));
            }
        } else {
            for (int t = tid; t < NN; t += TPB)
                sZU1[t] = make_float2(r1Z[t], __ldcg(src1 + t));
            Mv1 = decf(__ldcg(mvS1));
        }
    }
    if (act2) {
        if (fs2) {
            for (int t = tid; t < NN; t += TPB) {
                float2 xy = r2XY[t]; float z = r2Z[t];
                sZU2[t] = make_float2(z,
                    C_AL2E - C_KK * fmaf(xy.x, xy.x, fmaf(xy.y, xy.y, z * z)));
            }
        } else {
            for (int t = tid; t < NN; t += TPB)
                sZU2[t] = make_float2(r2Z[t], __ldcg(src2 + t));
            Mv2 = decf(__ldcg(mvS2));
        }
    }
    __syncthreads();

    const int w = tid >> 5, lane = tid & 31;
    const int grp = w >> 2, split = w & 3;
    const int j0 = colbase + grp * 8;
    const bool valid = (j0 < NN);

    if (valid && act1)
        col_sums8(r1XY, sZU1, c1XY, c1Z, Mv1, sPart + grp * 32, j0, split, lane);
    if (valid && act2)
        col_sums8(r2XY, sZU2, c2XY, c2Z, Mv2, sPart + 224 + grp * 32, j0, split, lane);
    __syncthreads();

    if (valid && split == 0) {
        if (act1)
            epi8(sPart + grp * 32, Mv1, c1XY, c1Z, j0, lane, dst1, fd1, err1, mvD1);
        if (act2)
            epi8(sPart + 224 + grp * 32, Mv2, c2XY, c2Z, j0, lane, dst2, fd2, err2, mvD2);
    }
}

// cost = sum_ij exp(A_j + B_i - C_ij/eps) * C_ij (accumulated; /(n*m) at end)
__device__ void cost_pass(
    const float2* rXY, const float* rZ,
    const float2* cXY, const float* cZ,
    float2* sZU, float* sPart,
    const float* srcU, const float* srcColU,
    float* costslot, int colbase)
{
    const int tid = threadIdx.x;
    for (int t = tid; t < NN; t += TPB)
        sZU[t] = make_float2(rZ[t], __ldcg(srcU + t) + 2.0f);
    __syncthreads();

    const int w = tid >> 5, lane = tid & 31;
    const int grp = w >> 2, split = w & 3;
    const int j0 = colbase + grp * 8;
    const bool valid = (j0 < NN);

    float v = 0.f;
    if (valid) {
        for (int ch = 0; ch < 2; ch++) {
            const int jb = j0 + ch * 4;
            float qx[4], qy[4], qz[4], cp[4], qq[4], a1[4], a2[4];
#pragma unroll
            for (int t = 0; t < 4; t++) {
                float2 q = cXY[jb + t]; float z = cZ[jb + t];
                qq[t] = fmaf(q.x, q.x, fmaf(q.y, q.y, z * z));
                qx[t] = q.x * C_2K; qy[t] = q.y * C_2K; qz[t] = z * C_2K;
                cp[t] = __ldcg(srcColU + jb + t) + 2.0f;
                a1[t] = 0.f; a2[t] = 0.f;
            }
            int idx = split * (NN / NSPL) + lane;
#pragma unroll 2
            for (int k = 0; k < NN / NSPL / 32; k++, idx += 32) {
                float2 xy = rXY[idx];
                float2 zu = sZU[idx];
                float x = xy.x, y = xy.y, z = zu.x, u = zu.y;
                float rr = fmaf(x, x, fmaf(y, y, z * z));
#pragma unroll
                for (int t = 0; t < 4; t++) {
                    float ww = fmaf(x, qx[t], fmaf(y, qy[t], fmaf(z, qz[t], u)));
                    float ev = ex2f_(ww + cp[t]);
                    float Xv = fmaf(u - ww, C_INVK, rr);
                    a1[t] = fmaf(ev, Xv, a1[t]);
                    a2[t] += ev;
                }
            }
#pragma unroll
            for (int t = 0; t < 4; t++) v += a1[t] + qq[t] * a2[t];
        }
    }
#pragma unroll
    for (int o = 16; o > 0; o >>= 1)
        v += __shfl_xor_sync(0xffffffffu, v, o);
    if (lane == 0) sPart[w] = v;
    __syncthreads();
    if (tid == 0) {
        float s = 0.f;
#pragma unroll
        for (int q = 0; q < TPB / 32; q++) s += sPart[q];
        atomicAdd(costslot, s);
    }
    __syncthreads();
}

// chamfer: per own-point j, min over iter-points i of |r_i - q_j|^2
__device__ void cham_pass(
    const float2* iXY, const float* iZ,
    const float2* oXY, const float* oZ,
    float* sPart, float* accum, int colbase)
{
    const int tid = threadIdx.x, w = tid >> 5, lane = tid & 31;
    const int grp = w >> 2, split = w & 3;
    const int j0 = colbase + grp * 8;
    const bool valid = (j0 < NN);

    if (valid) {
        for (int ch = 0; ch < 2; ch++) {
            const int jb = j0 + ch * 4;
            float qx[4], qy[4], qz[4], m[4];
#pragma unroll
            for (int t = 0; t < 4; t++) {
                float2 q = oXY[jb + t]; float z = oZ[jb + t];
                qx[t] = -2.f * q.x; qy[t] = -2.f * q.y; qz[t] = -2.f * z;
                m[t] = 3.4e38f;
            }
            int idx = split * (NN / NSPL) + lane;
            for (int k = 0; k < NN / NSPL / 32; k++, idx += 32) {
                float2 xy = iXY[idx]; float z = iZ[idx];
                float rr = fmaf(xy.x, xy.x, fmaf(xy.y, xy.y, z * z));
#pragma unroll
                for (int t = 0; t < 4; t++) {
                    float vv = fmaf(xy.x, qx[t], fmaf(xy.y, qy[t], fmaf(z, qz[t], rr)));
                    m[t] = fminf(m[t], vv);
                }
            }
#pragma unroll
            for (int o = 16; o > 0; o >>= 1)
#pragma unroll
                for (int t = 0; t < 4; t++)
                    m[t] = fminf(m[t], __shfl_xor_sync(0xffffffffu, m[t], o));
            if (lane == 0) {
#pragma unroll
                for (int t = 0; t < 4; t++)
                    sPart[grp * 32 + split * 8 + ch * 4 + t] = m[t];
            }
        }
    }
    __syncthreads();
    if (valid && split == 0) {
        float s = 0.f;
        if (lane < 8) {
            float mm = fminf(fminf(sPart[grp * 32 + lane], sPart[grp * 32 + 8 + lane]),
                             fminf(sPart[grp * 32 + 16 + lane], sPart[grp * 32 + 24 + lane]));
            float2 q = oXY[j0 + lane]; float z = oZ[j0 + lane];
            s = mm + fmaf(q.x, q.x, fmaf(q.y, q.y, z * z));
        }
#pragma unroll
        for (int o = 16; o > 0; o >>= 1)
            s += __shfl_xor_sync(0xffffffffu, s, o);
        if (lane == 0) atomicAdd(accum, s);
    }
    __syncthreads();
}

__global__ void __launch_bounds__(TPB, 1)
emd_kernel(const float* __restrict__ preds, const float* __restrict__ gts,
           float* __restrict__ out, int out_size)
{
    extern __shared__ float sm[];
    float2* sGXY = (float2*)sm;
    float2* sPXY = (float2*)(sm + 2 * NN);
    float*  sGZ  = sm + 4 * NN;
    float*  sPZ  = sm + 5 * NN;
    float2* sZU1 = (float2*)(sm + 6 * NN);
    float2* sZU2 = (float2*)(sm + 8 * NN);
    float*  sPart = sm + 10 * NN;       // 512 floats; [448],[449] = act flags

    const int b       = blockIdx.x / CTAB;
    const int slot    = blockIdx.x % CTAB;
    const int colbase = slot * CPC;
    const int tid     = threadIdx.x;

    const float* gp = gts + (size_t)b * NN * 3;
    const float* pp = preds + (size_t)b * NN * 3;
    for (int i = tid; i < NN; i += TPB) {
        sGXY[i] = make_float2(gp[3 * i + 0], gp[3 * i + 1]);
        sGZ[i]  = gp[3 * i + 2];
        sPXY[i] = make_float2(pp[3 * i + 0], pp[3 * i + 1]);
        sPZ[i]  = pp[3 * i + 2];
    }
    __syncthreads();

    unsigned lb = 0;

    cham_pass(sGXY, sGZ, sPXY, sPZ, sPart, &g_s.cham[b], colbase);
    cham_pass(sPXY, sPZ, sGXY, sGZ, sPart, &g_s.cham[NB + b], colbase);

    float* AU1 = g_s.AU1 + b * NN;  float* BU1 = g_s.BU1 + b * NN;
    float* AU2 = g_s.AU2 + b * NN;  float* BU2 = g_s.BU2 + b * NN;
    const int off1 = 0, off2 = NITS_K * NB;

    // Interleaved Sinkhorn: run1 = C(gts,preds), run2 = C(preds,preds).
    bool act1 = true, act2 = true;
    int it1 = 0, it2 = 0;
    while (act1 || act2) {
        // A-halves: sum over rows, write A (columns)
        dual_half(act1, sGXY, sGZ, sPXY, sPZ, BU1, AU1,
                  &g_s.mvB[off1 + (it1 == 0 ? 0 : (it1 - 1) * NB) + b],
                  &g_s.mvA[off1 + it1 * NB + b],
                  &g_s.errA[off1 + it1 * NB + b], it1 == 0, it1 == 0,
                  act2, sPXY, sPZ, sPXY, sPZ, BU2, AU2,
                  &g_s.mvB[off2 + (it2 == 0 ? 0 : (it2 - 1) * NB) + b],
                  &g_s.mvA[off2 + it2 * NB + b],
                  &g_s.errA[off2 + it2 * NB + b], it2 == 0, it2 == 0,
                  sZU1, sZU2, sPart, colbase);
        grid_barrier(lb);
        // B-halves: sum over cols, write B (rows)
        dual_half(act1, sPXY, sPZ, sGXY, sGZ, AU1, BU1,
                  &g_s.mvA[off1 + it1 * NB + b],
                  &g_s.mvB[off1 + it1 * NB + b],
                  &g_s.errB[off1 + it1 * NB + b], false, it1 == 0,
                  act2, sPXY, sPZ, sPXY, sPZ, AU2, BU2,
                  &g_s.mvA[off2 + it2 * NB + b],
                  &g_s.mvB[off2 + it2 * NB + b],
                  &g_s.errB[off2 + it2 * NB + b], false, it2 == 0,
                  sZU1, sZU2, sPart, colbase);
        grid_barrier(lb);

        // convergence check: thread0 only, broadcast via smem
        if (tid == 0) {
            float c1 = 0.f, c2 = 0.f;
            if (act1) {
                float ae = 0.f, be = 0.f;
#pragma unroll
                for (int bb = 0; bb < NB; bb++) {
                    ae = fmaxf(ae, __ldcg(&g_s.errA[off1 + it1 * NB + bb]));
                    be = fmaxf(be, __ldcg(&g_s.errB[off1 + it1 * NB + bb]));
                }
                ae *= (C_EPS / (float)NN); be *= (C_EPS / (float)NN);
                c1 = ((it1 + 1) < NITS_K && (ae >= C_TOL || be >= C_TOL)) ? 1.f : 0.f;
            }
            if (act2) {
                float ae = 0.f, be = 0.f;
#pragma unroll
                for (int bb = 0; bb < NB; bb++) {
                    ae = fmaxf(ae, __ldcg(&g_s.errA[off2 + it2 * NB + bb]));
                    be = fmaxf(be, __ldcg(&g_s.errB[off2 + it2 * NB + bb]));
                }
                ae *= (C_EPS / (float)NN); be *= (C_EPS / (float)NN);
                c2 = ((it2 + 1) < NITS_K && (ae >= C_TOL || be >= C_TOL)) ? 1.f : 0.f;
            }
            sPart[448] = c1; sPart[449] = c2;
        }
        __syncthreads();
        if (act1) { it1++; act1 = (sPart[448] != 0.f); }
        if (act2) { it2++; act2 = (sPart[449] != 0.f); }
        __syncthreads();
    }

    // cost passes on the final potentials
    cost_pass(sGXY, sGZ, sPXY, sPZ, sZU1, sPart, BU1, AU1, &g_s.cost[b], colbase);
    cost_pass(sPXY, sPZ, sPXY, sPZ, sZU1, sPart, BU2, AU2, &g_s.cost[NB + b], colbase);

    grid_barrier(lb);

    if (blockIdx.x == 0 && tid == 0) {
        const float inv_nm = 1.0f / ((float)NN * (float)NN);
        for (int bb = 0; bb < NB && bb < out_size; bb++) {
            float c1 = __ldcg(&g_s.cost[bb]);
            float c2 = __ldcg(&g_s.cost[NB + bb]);
            out[bb] = (c1 - 0.5f * c2) * inv_nm;
        }
        if (out_size >= 5) {
            float ch = 0.f;
            for (int bb = 0; bb < NB; bb++)
                ch += __ldcg(&g_s.cham[bb]) + __ldcg(&g_s.cham[NB + bb]);
            out[4] = ch / (float)(NB * NN);
        }
    }
}

extern "C" void kernel_launch(void* const* d_in, const int* in_sizes, int n_in,
                              void* d_out, int out_size)
{
    const float* preds = (const float*)d_in[0];
    const float* gts   = (const float*)d_in[1];
    float* out = (float*)d_out;

    void* sptr = nullptr;
    cudaGetSymbolAddress(&sptr, g_s);
    cudaMemsetAsync(sptr, 0, sizeof(ScratchT), 0);

    const int smem = (int)((10 * NN + 512) * sizeof(float));
    cudaFuncSetAttribute(emd_kernel, cudaFuncAttributeMaxDynamicSharedMemorySize, smem);
    emd_kernel<<<NCTA, TPB, smem, 0>>>(preds, gts, out, out_size);
}

// round 10
// speedup vs baseline: 1.0749x; 1.0749x over previous
#include <cuda_runtime.h>
#include <cstdint>
#include <cstddef>

#define NB 4
#define NN 2048
#define CTAB 37                 // CTAs per batch
#define NCTA (NB * CTAB)        // 148 = one per SM
#define TPB 896                 // 28 warps = 7 col-groups x 4 range-splits
#define NSPL 4
#define CPC 56                  // columns per CTA (last CTA of batch: 32)
#define NITS_K 50

typedef unsigned long long u64;

constexpr float C_EPS  = 0.1f;
constexpr float C_TOL  = 1e-3f;
constexpr float C_L2E  = 1.4426950408889634f;
constexpr float C_KK   = C_L2E / C_EPS;
constexpr float C_2K   = 2.0f * C_KK;
constexpr float C_INVK = C_EPS / C_L2E;
constexpr float C_LN2  = 0.6931471805599453f;
constexpr float C_AL2E = -2.0f;                  // log2(1/4)

struct ScratchT {
    unsigned barcnt;
    unsigned pad[31];
    float AU1[NB * NN];
    float BU1[NB * NN];
    float AU2[NB * NN];
    float BU2[NB * NN];
    float errA[2 * NITS_K * NB];
    float errB[2 * NITS_K * NB];
    unsigned mvA[2 * NITS_K * NB];
    unsigned mvB[2 * NITS_K * NB];
    float cost[2 * NB];
    float cham[2 * NB];
};
__device__ ScratchT g_s;

__device__ __forceinline__ float ex2f_(float x) {
    float y; asm("ex2.approx.ftz.f32 %0, %1;" : "=f"(y) : "f"(x)); return y;
}
__device__ __forceinline__ float lg2f_(float x) {
    float y; asm("lg2.approx.f32 %0, %1;" : "=f"(y) : "f"(x)); return y;
}
__device__ __forceinline__ u64 pk2(float lo, float hi) {
    u64 r; asm("mov.b64 %0, {%1, %2};" : "=l"(r) : "f"(lo), "f"(hi)); return r;
}
__device__ __forceinline__ void upk(u64 v, float& lo, float& hi) {
    asm("mov.b64 {%0, %1}, %2;" : "=f"(lo), "=f"(hi) : "l"(v));
}
__device__ __forceinline__ u64 pfma(u64 a, u64 b, u64 c) {
    u64 d; asm("fma.rn.f32x2 %0, %1, %2, %3;" : "=l"(d) : "l"(a), "l"(b), "l"(c)); return d;
}
__device__ __forceinline__ u64 padd(u64 a, u64 b) {
    u64 d; asm("add.rn.f32x2 %0, %1, %2;" : "=l"(d) : "l"(a), "l"(b)); return d;
}
__device__ __forceinline__ unsigned encf(float f) {
    unsigned u = __float_as_uint(f);
    return (u & 0x80000000u) ? ~u : (u | 0x80000000u);
}
__device__ __forceinline__ float decf(unsigned e) {
    return (e & 0x80000000u) ? __uint_as_float(e & 0x7fffffffu) : __uint_as_float(~e);
}

// grid barrier: 148 CTAs, one per SM. Single monotonic counter.
__device__ __forceinline__ void grid_barrier(unsigned& lb) {
    __syncthreads();
    lb++;
    if (threadIdx.x == 0) {
        unsigned target = lb * (unsigned)NCTA;
        asm volatile("red.release.gpu.global.add.u32 [%0], %1;"
                     :: "l"(&g_s.barcnt), "r"(1u) : "memory");
        unsigned v;
        do {
            asm volatile("ld.acquire.gpu.global.u32 %0, [%1];"
                         : "=r"(v) : "l"(&g_s.barcnt) : "memory");
        } while (v < target);
    }
    __syncthreads();
}

// One Sinkhorn half-update, log2 domain, u'-form potentials:
//   stored u'_j = (v_j + alpha)*log2e - k*|q_j|^2
//   v_j = -ln2*(Mv + log2 sum_i 2^(u'_i + 2k r_i.q_j - k|q_j|^2 - Mv))
//   Mv = max_i p_i,  p_i = (v_i + alpha)*log2e
// NOTE: no trailing __syncthreads — the caller supplies the separator
// (explicit sync between run1/run2 calls, grid_barrier otherwise).
__device__ void half_update(
    const float2* rXY, const float* rZ,
    const float2* cXY, const float* cZ,
    float2* sZU, float* sPart,
    const float* srcU, float* dstU,
    const unsigned* mvSrc, unsigned* mvDst, float* errSlot,
    bool firstSrc, bool firstDst, int colbase)
{
    const int tid = threadIdx.x;

    if (firstSrc) {
        for (int t = tid; t < NN; t += TPB) {
            float2 xy = rXY[t]; float z = rZ[t];
            float u = C_AL2E - C_KK * fmaf(xy.x, xy.x, fmaf(xy.y, xy.y, z * z));
            sZU[t] = make_float2(z, u);
        }
    } else {
        for (int t = tid; t < NN; t += TPB)
            sZU[t] = make_float2(rZ[t], __ldcg(srcU + t));
    }
    const float Mv = firstSrc ? C_AL2E : decf(__ldcg(mvSrc));
    __syncthreads();

    const int w = tid >> 5, lane = tid & 31;
    const int grp = w >> 2, split = w & 3;
    const int j0 = colbase + grp * 8;
    const bool valid = (j0 < NN);

    if (valid) {
        u64 qx2[4], qy2[4], qz2[4], dj2[4];
        float sal[8];
#pragma unroll
        for (int p = 0; p < 4; p++) {
            float2 qa = cXY[j0 + 2 * p], qb = cXY[j0 + 2 * p + 1];
            float za = cZ[j0 + 2 * p], zb = cZ[j0 + 2 * p + 1];
            float qqa = fmaf(qa.x, qa.x, fmaf(qa.y, qa.y, za * za));
            float qqb = fmaf(qb.x, qb.x, fmaf(qb.y, qb.y, zb * zb));
            qx2[p] = pk2(qa.x * C_2K, qb.x * C_2K);
            qy2[p] = pk2(qa.y * C_2K, qb.y * C_2K);
            qz2[p] = pk2(za * C_2K, zb * C_2K);
            dj2[p] = pk2(-C_KK * qqa - Mv, -C_KK * qqb - Mv);
            sal[2 * p] = 0.f; sal[2 * p + 1] = 0.f;
        }

        int idx = split * (NN / NSPL) + lane;
#pragma unroll 4
        for (int k = 0; k < NN / NSPL / 32; k++, idx += 32) {
            float2 xy = rXY[idx];
            float2 zu = sZU[idx];
            u64 X2 = pk2(xy.x, xy.x), Y2 = pk2(xy.y, xy.y);
            u64 Z2 = pk2(zu.x, zu.x), U2 = pk2(zu.y, zu.y);
#pragma unroll
            for (int p = 0; p < 4; p++) {
                u64 t0 = padd(U2, dj2[p]);
                t0 = pfma(Z2, qz2[p], t0);
                t0 = pfma(Y2, qy2[p], t0);
                t0 = pfma(X2, qx2[p], t0);
                float lo, hi; upk(t0, lo, hi);
                sal[2 * p]     += ex2f_(lo);
                sal[2 * p + 1] += ex2f_(hi);
            }
        }
#pragma unroll
        for (int o = 16; o > 0; o >>= 1)
#pragma unroll
            for (int c = 0; c < 8; c++)
                sal[c] += __shfl_xor_sync(0xffffffffu, sal[c], o);
        if (lane == 0) {
#pragma unroll
            for (int c = 0; c < 8; c++)
                sPart[grp * 32 + split * 8 + c] = sal[c];
        }
    }
    __syncthreads();

    if (valid && split == 0) {
        float e = 0.f, pm = -3.4e38f;
        if (lane < 8) {
            float s = sPart[grp * 32 + lane] + sPart[grp * 32 + 8 + lane]
                    + sPart[grp * 32 + 16 + lane] + sPart[grp * 32 + 24 + lane];
            s = fmaxf(s, 1e-35f);
            float L = Mv + lg2f_(s);
            float pnew = C_AL2E - L;
            float2 q = cXY[j0 + lane]; float z = cZ[j0 + lane];
            float qq = fmaf(q.x, q.x, fmaf(q.y, q.y, z * z));
            float unew = pnew - C_KK * qq;
            float pold = firstDst ? C_AL2E
                                  : (__ldcg(dstU + j0 + lane) + C_KK * qq);
            e = fabsf(pnew - pold);
            pm = pnew;
            __stcg(dstU + j0 + lane, unew);
        }
#pragma unroll
        for (int o = 16; o > 0; o >>= 1) {
            e += __shfl_xor_sync(0xffffffffu, e, o);
            pm = fmaxf(pm, __shfl_xor_sync(0xffffffffu, pm, o));
        }
        if (lane == 0) {
            atomicAdd(errSlot, e * C_LN2);
            atomicMax(mvDst, encf(pm));
        }
    }
    // no trailing sync — caller separates
}

// cost = sum_ij exp(A_j + B_i - C_ij/eps) * C_ij (accumulated; /(n*m) at end)
__device__ void cost_pass(
    const float2* rXY, const float* rZ,
    const float2* cXY, const float* cZ,
    float2* sZU, float* sPart,
    const float* srcU, const float* srcColU,
    float* costslot, int colbase)
{
    const int tid = threadIdx.x;
    for (int t = tid; t < NN; t += TPB)
        sZU[t] = make_float2(rZ[t], __ldcg(srcU + t) + 2.0f);
    __syncthreads();

    const int w = tid >> 5, lane = tid & 31;
    const int grp = w >> 2, split = w & 3;
    const int j0 = colbase + grp * 8;
    const bool valid = (j0 < NN);

    float v = 0.f;
    if (valid) {
        for (int ch = 0; ch < 2; ch++) {
            const int jb = j0 + ch * 4;
            float qx[4], qy[4], qz[4], cp[4], qq[4], a1[4], a2[4];
#pragma unroll
            for (int t = 0; t < 4; t++) {
                float2 q = cXY[jb + t]; float z = cZ[jb + t];
                qq[t] = fmaf(q.x, q.x, fmaf(q.y, q.y, z * z));
                qx[t] = q.x * C_2K; qy[t] = q.y * C_2K; qz[t] = z * C_2K;
                cp[t] = __ldcg(srcColU + jb + t) + 2.0f;
                a1[t] = 0.f; a2[t] = 0.f;
            }
            int idx = split * (NN / NSPL) + lane;
#pragma unroll 2
            for (int k = 0; k < NN / NSPL / 32; k++, idx += 32) {
                float2 xy = rXY[idx];
                float2 zu = sZU[idx];
                float x = xy.x, y = xy.y, z = zu.x, u = zu.y;
                float rr = fmaf(x, x, fmaf(y, y, z * z));
#pragma unroll
                for (int t = 0; t < 4; t++) {
                    float ww = fmaf(x, qx[t], fmaf(y, qy[t], fmaf(z, qz[t], u)));
                    float ev = ex2f_(ww + cp[t]);
                    float Xv = fmaf(u - ww, C_INVK, rr);
                    a1[t] = fmaf(ev, Xv, a1[t]);
                    a2[t] += ev;
                }
            }
#pragma unroll
            for (int t = 0; t < 4; t++) v += a1[t] + qq[t] * a2[t];
        }
    }
#pragma unroll
    for (int o = 16; o > 0; o >>= 1)
        v += __shfl_xor_sync(0xffffffffu, v, o);
    if (lane == 0) sPart[w] = v;
    __syncthreads();
    if (tid == 0) {
        float s = 0.f;
#pragma unroll
        for (int q = 0; q < TPB / 32; q++) s += sPart[q];
        atomicAdd(costslot, s);
    }
    __syncthreads();
}

// chamfer: per own-point j, min over iter-points i of |r_i - q_j|^2
__device__ void cham_pass(
    const float2* iXY, const float* iZ,
    const float2* oXY, const float* oZ,
    float* sPart, float* accum, int colbase)
{
    const int tid = threadIdx.x, w = tid >> 5, lane = tid & 31;
    const int grp = w >> 2, split = w & 3;
    const int j0 = colbase + grp * 8;
    const bool valid = (j0 < NN);

    if (valid) {
        for (int ch = 0; ch < 2; ch++) {
            const int jb = j0 + ch * 4;
            float qx[4], qy[4], qz[4], m[4];
#pragma unroll
            for (int t = 0; t < 4; t++) {
                float2 q = oXY[jb + t]; float z = oZ[jb + t];
                qx[t] = -2.f * q.x; qy[t] = -2.f * q.y; qz[t] = -2.f * z;
                m[t] = 3.4e38f;
            }
            int idx = split * (NN / NSPL) + lane;
            for (int k = 0; k < NN / NSPL / 32; k++, idx += 32) {
                float2 xy = iXY[idx]; float z = iZ[idx];
                float rr = fmaf(xy.x, xy.x, fmaf(xy.y, xy.y, z * z));
#pragma unroll
                for (int t = 0; t < 4; t++) {
                    float vv = fmaf(xy.x, qx[t], fmaf(xy.y, qy[t], fmaf(z, qz[t], rr)));
                    m[t] = fminf(m[t], vv);
                }
            }
#pragma unroll
            for (int o = 16; o > 0; o >>= 1)
#pragma unroll
                for (int t = 0; t < 4; t++)
                    m[t] = fminf(m[t], __shfl_xor_sync(0xffffffffu, m[t], o));
            if (lane == 0) {
#pragma unroll
                for (int t = 0; t < 4; t++)
                    sPart[grp * 32 + split * 8 + ch * 4 + t] = m[t];
            }
        }
    }
    __syncthreads();
    if (valid && split == 0) {
        float s = 0.f;
        if (lane < 8) {
            float mm = fminf(fminf(sPart[grp * 32 + lane], sPart[grp * 32 + 8 + lane]),
                             fminf(sPart[grp * 32 + 16 + lane], sPart[grp * 32 + 24 + lane]));
            float2 q = oXY[j0 + lane]; float z = oZ[j0 + lane];
            s = mm + fmaf(q.x, q.x, fmaf(q.y, q.y, z * z));
        }
#pragma unroll
        for (int o = 16; o > 0; o >>= 1)
            s += __shfl_xor_sync(0xffffffffu, s, o);
        if (lane == 0) atomicAdd(accum, s);
    }
    __syncthreads();
}

__global__ void __launch_bounds__(TPB, 1)
emd_kernel(const float* __restrict__ preds, const float* __restrict__ gts,
           float* __restrict__ out, int out_size)
{
    extern __shared__ float sm[];
    float2* sGXY = (float2*)sm;
    float2* sPXY = (float2*)(sm + 2 * NN);
    float*  sGZ  = sm + 4 * NN;
    float*  sPZ  = sm + 5 * NN;
    float2* sZU  = (float2*)(sm + 6 * NN);
    float*  sPart = sm + 8 * NN;       // 256 floats; [248],[249] = act flags

    const int b       = blockIdx.x / CTAB;
    const int slot    = blockIdx.x % CTAB;
    const int colbase = slot * CPC;
    const int tid     = threadIdx.x;

    const float* gp = gts + (size_t)b * NN * 3;
    const float* pp = preds + (size_t)b * NN * 3;
    for (int i = tid; i < NN; i += TPB) {
        sGXY[i] = make_float2(gp[3 * i + 0], gp[3 * i + 1]);
        sGZ[i]  = gp[3 * i + 2];
        sPXY[i] = make_float2(pp[3 * i + 0], pp[3 * i + 1]);
        sPZ[i]  = pp[3 * i + 2];
    }
    __syncthreads();

    unsigned lb = 0;

    cham_pass(sGXY, sGZ, sPXY, sPZ, sPart, &g_s.cham[b], colbase);
    cham_pass(sPXY, sPZ, sGXY, sGZ, sPart, &g_s.cham[NB + b], colbase);

    float* AU1 = g_s.AU1 + b * NN;  float* BU1 = g_s.BU1 + b * NN;
    float* AU2 = g_s.AU2 + b * NN;  float* BU2 = g_s.BU2 + b * NN;
    const int off1 = 0, off2 = NITS_K * NB;

    // Interleaved Sinkhorn: run1 = C(gts,preds), run2 = C(preds,preds).
    // Independent loops share the barrier cadence; per-run act flags
    // reproduce each reference while_loop's exact iteration count.
    bool act1 = true, act2 = true;
    int it1 = 0, it2 = 0;
    while (act1 || act2) {
        // A-halves: sum over rows, write A (columns)
        if (act1)
            half_update(sGXY, sGZ, sPXY, sPZ, sZU, sPart, BU1, AU1,
                        &g_s.mvB[off1 + (it1 == 0 ? 0 : (it1 - 1) * NB) + b],
                        &g_s.mvA[off1 + it1 * NB + b],
                        &g_s.errA[off1 + it1 * NB + b],
                        it1 == 0, it1 == 0, colbase);
        __syncthreads();    // separate shared sZU/sPart between the two runs
        if (act2)
            half_update(sPXY, sPZ, sPXY, sPZ, sZU, sPart, BU2, AU2,
                        &g_s.mvB[off2 + (it2 == 0 ? 0 : (it2 - 1) * NB) + b],
                        &g_s.mvA[off2 + it2 * NB + b],
                        &g_s.errA[off2 + it2 * NB + b],
                        it2 == 0, it2 == 0, colbase);
        grid_barrier(lb);
        // B-halves: sum over cols, write B (rows)
        if (act1)
            half_update(sPXY, sPZ, sGXY, sGZ, sZU, sPart, AU1, BU1,
                        &g_s.mvA[off1 + it1 * NB + b],
                        &g_s.mvB[off1 + it1 * NB + b],
                        &g_s.errB[off1 + it1 * NB + b],
                        false, it1 == 0, colbase);
        __syncthreads();
        if (act2)
            half_update(sPXY, sPZ, sPXY, sPZ, sZU, sPart, AU2, BU2,
                        &g_s.mvA[off2 + it2 * NB + b],
                        &g_s.mvB[off2 + it2 * NB + b],
                        &g_s.errB[off2 + it2 * NB + b],
                        false, it2 == 0, colbase);
        grid_barrier(lb);

        // convergence check: thread0 only, broadcast via smem
        if (tid == 0) {
            float c1 = 0.f, c2 = 0.f;
            if (act1) {
                float ae = 0.f, be = 0.f;
#pragma unroll
                for (int bb = 0; bb < NB; bb++) {
                    ae = fmaxf(ae, __ldcg(&g_s.errA[off1 + it1 * NB + bb]));
                    be = fmaxf(be, __ldcg(&g_s.errB[off1 + it1 * NB + bb]));
                }
                ae *= (C_EPS / (float)NN); be *= (C_EPS / (float)NN);
                c1 = ((it1 + 1) < NITS_K && (ae >= C_TOL || be >= C_TOL)) ? 1.f : 0.f;
            }
            if (act2) {
                float ae = 0.f, be = 0.f;
#pragma unroll
                for (int bb = 0; bb < NB; bb++) {
                    ae = fmaxf(ae, __ldcg(&g_s.errA[off2 + it2 * NB + bb]));
                    be = fmaxf(be, __ldcg(&g_s.errB[off2 + it2 * NB + bb]));
                }
                ae *= (C_EPS / (float)NN); be *= (C_EPS / (float)NN);
                c2 = ((it2 + 1) < NITS_K && (ae >= C_TOL || be >= C_TOL)) ? 1.f : 0.f;
            }
            sPart[248] = c1; sPart[249] = c2;
        }
        __syncthreads();
        if (act1) { it1++; act1 = (sPart[248] != 0.f); }
        if (act2) { it2++; act2 = (sPart[249] != 0.f); }
        // no trailing sync needed: flags are next rewritten only after two
        // grid barriers, and col_sums never touches sPart[248..249]
    }

    // cost passes on the final potentials
    cost_pass(sGXY, sGZ, sPXY, sPZ, sZU, sPart, BU1, AU1, &g_s.cost[b], colbase);
    cost_pass(sPXY, sPZ, sPXY, sPZ, sZU, sPart, BU2, AU2, &g_s.cost[NB + b], colbase);

    grid_barrier(lb);

    if (blockIdx.x == 0 && tid == 0) {
        const float inv_nm = 1.0f / ((float)NN * (float)NN);
        for (int bb = 0; bb < NB && bb < out_size; bb++) {
            float c1 = __ldcg(&g_s.cost[bb]);
            float c2 = __ldcg(&g_s.cost[NB + bb]);
            out[bb] = (c1 - 0.5f * c2) * inv_nm;
        }
        if (out_size >= 5) {
            float ch = 0.f;
            for (int bb = 0; bb < NB; bb++)
                ch += __ldcg(&g_s.cham[bb]) + __ldcg(&g_s.cham[NB + bb]);
            out[4] = ch / (float)(NB * NN);
        }
    }
}

extern "C" void kernel_launch(void* const* d_in, const int* in_sizes, int n_in,
                              void* d_out, int out_size)
{
    const float* preds = (const float*)d_in[0];
    const float* gts   = (const float*)d_in[1];
    float* out = (float*)d_out;

    void* sptr = nullptr;
    cudaGetSymbolAddress(&sptr, g_s);
    cudaMemsetAsync(sptr, 0, sizeof(ScratchT), 0);

    const int smem = (int)((8 * NN + 256) * sizeof(float));
    cudaFuncSetAttribute(emd_kernel, cudaFuncAttributeMaxDynamicSharedMemorySize, smem);
    emd_kernel<<<NCTA, TPB, smem, 0>>>(preds, gts, out, out_size);
}